// round 9
// baseline (speedup 1.0000x reference)
#include <cuda_runtime.h>
#include <math.h>

#define BN   64
#define N1P  8192
#define NV   778
#define VP   780      // padded to multiple of 4
#define NFC  1538
#define NP   204      // prior subset size

#define PTS        2
#define TPB        128
#define MAIN_GX    32                      // 32 main tiles per batch (128*2*32=8192)
#define NTILE_MAIN (MAIN_GX * BN)          // 2048
#define NTILE_CHAM (4 * BN)                // 256 (2 dirs x 2 rowblocks)
#define CROWS      4
// tickets: 0 = slot-map, [1,65) normals, [65,2113) main, [2113,2369) chamfer
#define T_NORM     1
#define T_MAIN     (T_NORM + BN)           // 65
#define T_CHAM     (T_MAIN + NTILE_MAIN)   // 2113
#define NTILES     (T_CHAM + NTILE_CHAM)   // 2369
#define NBLOCKS    (148 * 8)               // 1184

__device__ float g_vn[BN * 3 * NV];
__device__ float g_part_main[NTILE_MAIN * 5];
__device__ float g_part_cham[NTILE_CHAM];
__device__ int   g_slot2orig[VP];
__device__ int   g_ticket = 0;
__device__ int   g_done = 0;
__device__ int   g_mapdone = 0;
__device__ int   g_fin = 0;

// PRIOR_IDX sorted ascending (204 entries)
__constant__ int c_prior_sorted[NP] = {
46,47,48,49,73,96,98,99,
164,165,166,167,194,195,223,237,238,280,281,298,301,317,320,
323,324,325,326,327,328,329,330,331,332,333,
340,341,342,343,344,345,346,347,348,349,350,351,352,353,354,355,
356,357,358,359,375,376,386,387,396,397,402,403,413,429,
433,434,435,436,437,438,439,440,441,442,443,444,
452,453,454,455,456,459,460,461,462,463,464,465,466,467,
468,469,470,471,484,485,486,496,497,506,507,513,514,524,
545,546,547,548,549,550,551,552,553,555,
563,564,565,566,567,570,572,573,574,575,576,577,578,
580,581,582,583,600,601,602,614,615,624,625,630,631,641,
663,664,665,666,667,668,670,672,
680,681,682,683,684,686,687,688,689,690,691,692,693,694,695,
697,698,699,700,712,713,714,715,
737,738,739,740,741,743,744,745,746,748,749,750,
753,754,755,756,757,758,759,760,761,762,763,764,765,766,767,768,
772,774,775,777};

typedef unsigned long long u64;

__device__ __forceinline__ u64 ffma2(u64 a, u64 b, u64 c) {
    u64 d;
    asm("fma.rn.f32x2 %0, %1, %2, %3;" : "=l"(d) : "l"(a), "l"(b), "l"(c));
    return d;
}
__device__ __forceinline__ u64 bcast2(float x) {
    u64 r;
    asm("mov.b64 %0, {%1, %2};" : "=l"(r) : "f"(x), "f"(x));
    return r;
}
__device__ __forceinline__ void unpack2f(u64 v, float& lo, float& hi) {
    asm("mov.b64 {%0, %1}, %2;" : "=f"(lo), "=f"(hi) : "l"(v));
}

__global__ __launch_bounds__(TPB, 8) void k_mega(const float* __restrict__ obj,
                                                 const float* __restrict__ recon,
                                                 const float* __restrict__ gt,
                                                 const int* __restrict__ faces,
                                                 const float* __restrict__ mean,
                                                 const float* __restrict__ logv,
                                                 const float* __restrict__ rp,
                                                 const float* __restrict__ xp,
                                                 float* __restrict__ out) {
    __shared__ __align__(16) float S[8 * VP];   // 24.96KB
    __shared__ float s_red[20];
    __shared__ int   s_tile;
    const int tid = threadIdx.x;

    while (true) {
        __syncthreads();
        if (tid == 0) s_tile = atomicAdd(&g_ticket, 1);
        __syncthreads();
        const int tile = s_tile;
        if (tile >= NTILES) break;

        if (tile == 0) {
            // ---------------- slot-map build ----------------
            for (int j = tid; j < NV; j += TPB) {
                int lo = 0, hi = NP;
                while (lo < hi) { int mid = (lo + hi) >> 1;
                    if (c_prior_sorted[mid] < j) lo = mid + 1; else hi = mid; }
                bool member = (lo < NP) && (c_prior_sorted[lo] == j);
                int slot = member ? lo : (NP + j - lo);
                g_slot2orig[slot] = j;
            }
            for (int s = NV + tid; s < VP; s += TPB) g_slot2orig[s] = -1;
            __syncthreads();
            __threadfence();
            if (tid == 0) atomicExch(&g_mapdone, 1);
        }
        else if (tile < T_MAIN) {
            // ---------------- normals tile ----------------
            const int b = tile - T_NORM;
            float* sx = S;          float* sy = S + NV;      float* sz = S + 2 * NV;
            float* nx = S + 3 * NV; float* ny = S + 4 * NV;  float* nz = S + 5 * NV;
            const float* rb = recon + (size_t)b * NV * 3;
            for (int v = tid; v < NV; v += TPB) {
                sx[v] = rb[3*v+0]; sy[v] = rb[3*v+1]; sz[v] = rb[3*v+2];
                nx[v] = 0.f; ny[v] = 0.f; nz[v] = 0.f;
            }
            __syncthreads();
            for (int f = tid; f < NFC; f += TPB) {
                int i0 = faces[3*f+0], i1 = faces[3*f+1], i2 = faces[3*f+2];
                float e1x = sx[i1]-sx[i0], e1y = sy[i1]-sy[i0], e1z = sz[i1]-sz[i0];
                float e2x = sx[i2]-sx[i0], e2y = sy[i2]-sy[i0], e2z = sz[i2]-sz[i0];
                float fx = e1y*e2z - e1z*e2y;
                float fy = e1z*e2x - e1x*e2z;
                float fz = e1x*e2y - e1y*e2x;
                atomicAdd(&nx[i0], fx); atomicAdd(&ny[i0], fy); atomicAdd(&nz[i0], fz);
                atomicAdd(&nx[i1], fx); atomicAdd(&ny[i1], fy); atomicAdd(&nz[i1], fz);
                atomicAdd(&nx[i2], fx); atomicAdd(&ny[i2], fy); atomicAdd(&nz[i2], fz);
            }
            __syncthreads();
            float* vb = g_vn + (size_t)b * 3 * NV;
            for (int v = tid; v < NV; v += TPB) {
                float x = nx[v], y = ny[v], z = nz[v];
                float inv = 1.f / (sqrtf(x*x + y*y + z*z) + 1e-12f);
                vb[v] = x*inv; vb[NV+v] = y*inv; vb[2*NV+v] = z*inv;
            }
            __syncthreads();
            __threadfence();
            if (tid == 0) atomicAdd(&g_done, 1);
        }
        else if (tile < T_CHAM) {
            // ---------------- main tile ----------------
            const int m  = tile - T_MAIN;
            const int b  = m >> 5;
            const int xt = m & 31;
            float* rmx = S;          float* rmy = S + VP;   float* rmz = S + 2*VP; float* rcc = S + 3*VP;
            float* tmx = S + 4*VP;   float* tmy = S + 5*VP; float* tmz = S + 6*VP; float* tcc = S + 7*VP;

            if (tid == 0) { while (*(volatile int*)&g_mapdone == 0) { } }
            __syncthreads();
            __threadfence();

            const float* rb = recon + (size_t)b * NV * 3;
            const float* gb = gt    + (size_t)b * NV * 3;
            for (int v = tid; v < VP; v += TPB) {
                int orig = g_slot2orig[v];
                if (orig >= 0) {
                    float x = rb[3*orig+0], y = rb[3*orig+1], z = rb[3*orig+2];
                    rmx[v] = -2.f*x; rmy[v] = -2.f*y; rmz[v] = -2.f*z;
                    rcc[v] = fmaf(z, z, fmaf(y, y, x*x));
                } else {
                    rmx[v]=0.f; rmy[v]=0.f; rmz[v]=0.f; rcc[v]=3e37f;
                }
                if (v < NV) {
                    float x = gb[3*v+0], y = gb[3*v+1], z = gb[3*v+2];
                    tmx[v] = -2.f*x; tmy[v] = -2.f*y; tmz[v] = -2.f*z;
                    tcc[v] = fmaf(z, z, fmaf(y, y, x*x));
                } else {
                    tmx[v]=0.f; tmy[v]=0.f; tmz[v]=0.f; tcc[v]=3e37f;
                }
            }
            __syncthreads();

            u64 AX[PTS], AY[PTS], AZ[PTS];
            float ox[PTS], oy[PTS], oz[PTS], a2s[PTS];
            {
                const int base = xt * (TPB * PTS) + tid;
                #pragma unroll
                for (int i = 0; i < PTS; i++) {
                    const float* o = obj + ((size_t)b * N1P + base + i * TPB) * 3;
                    ox[i] = o[0]; oy[i] = o[1]; oz[i] = o[2];
                    a2s[i] = fmaf(oz[i], oz[i], fmaf(oy[i], oy[i], ox[i]*ox[i]));
                    AX[i] = bcast2(ox[i]); AY[i] = bcast2(oy[i]); AZ[i] = bcast2(oz[i]);
                }
            }

            float dgt[PTS], mA[PTS], mr[PTS];
            int   bt[PTS];
            #pragma unroll
            for (int i = 0; i < PTS; i++) {
                dgt[i] = 3e38f; mA[i] = 3e38f; mr[i] = 3e38f; bt[i] = 0;
            }

            // gt sweep (tree-min)
            #pragma unroll 2
            for (int t = 0; t < VP; t += 4) {
                ulonglong2 X = *(const ulonglong2*)(tmx + t);
                ulonglong2 Y = *(const ulonglong2*)(tmy + t);
                ulonglong2 Z = *(const ulonglong2*)(tmz + t);
                ulonglong2 C = *(const ulonglong2*)(tcc + t);
                #pragma unroll
                for (int i = 0; i < PTS; i++) {
                    u64 d2 = ffma2(AZ[i], Z.x, ffma2(AY[i], Y.x, ffma2(AX[i], X.x, C.x)));
                    float lo1, hi1; unpack2f(d2, lo1, hi1);
                    d2 = ffma2(AZ[i], Z.y, ffma2(AY[i], Y.y, ffma2(AX[i], X.y, C.y)));
                    float lo2, hi2; unpack2f(d2, lo2, hi2);
                    dgt[i] = fminf(dgt[i], fminf(fminf(lo1, hi1), fminf(lo2, hi2)));
                }
            }

            // recon sweep, segment A: prior slots [0,204)
            #pragma unroll 2
            for (int t = 0; t < NP; t += 4) {
                ulonglong2 X = *(const ulonglong2*)(rmx + t);
                ulonglong2 Y = *(const ulonglong2*)(rmy + t);
                ulonglong2 Z = *(const ulonglong2*)(rmz + t);
                ulonglong2 C = *(const ulonglong2*)(rcc + t);
                #pragma unroll
                for (int i = 0; i < PTS; i++) {
                    u64 d2 = ffma2(AZ[i], Z.x, ffma2(AY[i], Y.x, ffma2(AX[i], X.x, C.x)));
                    float lo1, hi1; unpack2f(d2, lo1, hi1);
                    d2 = ffma2(AZ[i], Z.y, ffma2(AY[i], Y.y, ffma2(AX[i], X.y, C.y)));
                    float lo2, hi2; unpack2f(d2, lo2, hi2);
                    float h = fminf(fminf(lo1, hi1), fminf(lo2, hi2));
                    mA[i] = fminf(mA[i], h);
                    bool c = h < mr[i];
                    mr[i] = fminf(mr[i], h);
                    bt[i] = c ? t : bt[i];
                }
            }
            // segment B: slots [204,VP)
            #pragma unroll 2
            for (int t = NP; t < VP; t += 4) {
                ulonglong2 X = *(const ulonglong2*)(rmx + t);
                ulonglong2 Y = *(const ulonglong2*)(rmy + t);
                ulonglong2 Z = *(const ulonglong2*)(rmz + t);
                ulonglong2 C = *(const ulonglong2*)(rcc + t);
                #pragma unroll
                for (int i = 0; i < PTS; i++) {
                    u64 d2 = ffma2(AZ[i], Z.x, ffma2(AY[i], Y.x, ffma2(AX[i], X.x, C.x)));
                    float lo1, hi1; unpack2f(d2, lo1, hi1);
                    d2 = ffma2(AZ[i], Z.y, ffma2(AY[i], Y.y, ffma2(AX[i], X.y, C.y)));
                    float lo2, hi2; unpack2f(d2, lo2, hi2);
                    float h = fminf(fminf(lo1, hi1), fminf(lo2, hi2));
                    bool c = h < mr[i];
                    mr[i] = fminf(mr[i], h);
                    bt[i] = c ? t : bt[i];
                }
            }

            if (tid == 0) { while (*(volatile int*)&g_done < BN) { } }
            __syncthreads();
            __threadfence();

            float cm = 0.f, pen = 0.f, npn = 0.f, cons = 0.f, gtc = 0.f;
            const float* vb = g_vn + (size_t)b * 3 * NV;
            #pragma unroll
            for (int i = 0; i < PTS; i++) {
                const int t = bt[i];
                const float m2 = mr[i];
                int slot = t;
                #pragma unroll
                for (int jj = 3; jj >= 0; jj--) {
                    int j = t + jj;
                    float dj = fmaf(oz[i], rmz[j], fmaf(oy[i], rmy[j], fmaf(ox[i], rmx[j], rcc[j])));
                    if (dj == m2) slot = j;
                }
                const int idx = g_slot2orig[slot];
                float drec = fmaxf(m2 + a2s[i], 0.f);
                float dg   = fmaxf(dgt[i] + a2s[i], 0.f);
                float dpr  = fmaxf(mA[i] + a2s[i], 0.f);
                if (drec < 1e-4f) { cm += dpr; npn += 1.f; }
                bool rc = sqrtf(drec) < 0.005f;
                bool gc = sqrtf(dg)   < 0.005f;
                if (gc) { gtc += 1.f; if (rc) cons += 1.f; }
                float nvx = -0.5f * rmx[slot], nvy = -0.5f * rmy[slot], nvz = -0.5f * rmz[slot];
                float dot = (nvx - ox[i]) * __ldcg(vb + idx)
                          + (nvy - oy[i]) * __ldcg(vb + NV + idx)
                          + (nvz - oz[i]) * __ldcg(vb + 2 * NV + idx);
                if (dot > 0.f) pen += drec;
            }

            for (int off = 16; off; off >>= 1) {
                cm   += __shfl_down_sync(0xFFFFFFFFu, cm,   off);
                pen  += __shfl_down_sync(0xFFFFFFFFu, pen,  off);
                npn  += __shfl_down_sync(0xFFFFFFFFu, npn,  off);
                cons += __shfl_down_sync(0xFFFFFFFFu, cons, off);
                gtc  += __shfl_down_sync(0xFFFFFFFFu, gtc,  off);
            }
            const int wid = tid >> 5, lane = tid & 31;
            if (lane == 0) {
                s_red[wid]      = cm;   s_red[4 + wid]  = pen;
                s_red[8 + wid]  = npn;  s_red[12 + wid] = cons;
                s_red[16 + wid] = gtc;
            }
            __syncthreads();
            if (tid == 0) {
                float c = 0, p = 0, n = 0, co = 0, g = 0;
                for (int w = 0; w < 4; w++) {
                    c += s_red[w]; p += s_red[4+w]; n += s_red[8+w];
                    co += s_red[12+w]; g += s_red[16+w];
                }
                float* gp = g_part_main + (size_t)m * 5;
                gp[0] = c; gp[1] = p; gp[2] = n; gp[3] = co; gp[4] = g;
            }
        }
        else {
            // ---------------- chamfer tile: dir x rowblock ----------------
            const int c   = tile - T_CHAM;       // 0..255
            const int b   = c >> 2;
            const int dir = (c >> 1) & 1;
            const int rbk = c & 1;               // rowblock: rows [rbk*512, ...)
            const float* srcp = (dir ? gt : recon) + (size_t)b * NV * 3;
            const float* tgtp = (dir ? recon : gt) + (size_t)b * NV * 3;
            float* tmx = S;        float* tmy = S + VP;
            float* tmz = S + 2*VP; float* tcc = S + 3*VP;
            for (int v = tid; v < VP; v += TPB) {
                if (v < NV) {
                    float x = tgtp[3*v+0], y = tgtp[3*v+1], z = tgtp[3*v+2];
                    tmx[v] = -2.f*x; tmy[v] = -2.f*y; tmz[v] = -2.f*z;
                    tcc[v] = fmaf(z, z, fmaf(y, y, x*x));
                } else { tmx[v]=0.f; tmy[v]=0.f; tmz[v]=0.f; tcc[v]=3e37f; }
            }
            __syncthreads();

            u64 CAX[CROWS], CAY[CROWS], CAZ[CROWS];
            float ca2[CROWS];
            bool  cok[CROWS];
            #pragma unroll
            for (int s = 0; s < CROWS; s++) {
                int r = rbk * 512 + s * TPB + tid;
                cok[s] = (r < NV);
                float x = 0.f, y = 0.f, z = 0.f;
                if (cok[s]) { x = srcp[3*r+0]; y = srcp[3*r+1]; z = srcp[3*r+2]; }
                ca2[s] = fmaf(z, z, fmaf(y, y, x*x));
                CAX[s] = bcast2(x); CAY[s] = bcast2(y); CAZ[s] = bcast2(z);
            }
            float cm0[CROWS];
            #pragma unroll
            for (int s = 0; s < CROWS; s++) cm0[s] = 3e38f;

            #pragma unroll 1
            for (int t = 0; t < VP; t += 4) {
                ulonglong2 X = *(const ulonglong2*)(tmx + t);
                ulonglong2 Y = *(const ulonglong2*)(tmy + t);
                ulonglong2 Z = *(const ulonglong2*)(tmz + t);
                ulonglong2 C = *(const ulonglong2*)(tcc + t);
                #pragma unroll
                for (int s = 0; s < CROWS; s++) {
                    u64 d2 = ffma2(CAZ[s], Z.x, ffma2(CAY[s], Y.x, ffma2(CAX[s], X.x, C.x)));
                    float lo1, hi1; unpack2f(d2, lo1, hi1);
                    d2 = ffma2(CAZ[s], Z.y, ffma2(CAY[s], Y.y, ffma2(CAX[s], X.y, C.y)));
                    float lo2, hi2; unpack2f(d2, lo2, hi2);
                    cm0[s] = fminf(cm0[s], fminf(fminf(lo1, hi1), fminf(lo2, hi2)));
                }
            }
            float part = 0.f;
            #pragma unroll
            for (int s = 0; s < CROWS; s++)
                if (cok[s]) part += fmaxf(cm0[s] + ca2[s], 0.f);

            for (int off = 16; off; off >>= 1) part += __shfl_down_sync(0xFFFFFFFFu, part, off);
            if ((tid & 31) == 0) s_red[tid >> 5] = part;
            __syncthreads();
            if (tid == 0)
                g_part_cham[c] = s_red[0] + s_red[1] + s_red[2] + s_red[3];
        }
    }

    // ---------------- completion: last block does final combine ----------------
    __syncthreads();
    if (tid == 0) {
        __threadfence();
        int r = atomicAdd(&g_fin, 1);
        s_tile = (r == NBLOCKS - 1) ? 1 : 0;
    }
    __syncthreads();
    if (s_tile) {
        __threadfence();
        float sp = 0.f, sk = 0.f, sc = 0.f;
        float scm = 0.f, spe = 0.f, snp = 0.f, sco = 0.f, sgt = 0.f;
        for (int i = tid; i < BN * 61; i += TPB) { float d = rp[i] - xp[i]; sp += d * d; }
        for (int i = tid; i < BN * 64; i += TPB) {
            float m = mean[i], lv = logv[i];
            sk += 1.f + lv - m*m - expf(lv);
        }
        for (int i = tid; i < NTILE_CHAM; i += TPB) sc += g_part_cham[i];
        for (int i = tid; i < NTILE_MAIN; i += TPB) {
            const float* gp = g_part_main + (size_t)i * 5;
            scm += gp[0]; spe += gp[1]; snp += gp[2]; sco += gp[3]; sgt += gp[4];
        }
        for (int off = 16; off; off >>= 1) {
            sp  += __shfl_down_sync(0xFFFFFFFFu, sp,  off);
            sk  += __shfl_down_sync(0xFFFFFFFFu, sk,  off);
            sc  += __shfl_down_sync(0xFFFFFFFFu, sc,  off);
            scm += __shfl_down_sync(0xFFFFFFFFu, scm, off);
            spe += __shfl_down_sync(0xFFFFFFFFu, spe, off);
            snp += __shfl_down_sync(0xFFFFFFFFu, snp, off);
            sco += __shfl_down_sync(0xFFFFFFFFu, sco, off);
            sgt += __shfl_down_sync(0xFFFFFFFFu, sgt, off);
        }
        const int wid = tid >> 5;
        if ((tid & 31) == 0) {
            s_red[wid]      = sp;  s_red[4 + wid]  = sk;
            s_red[8 + wid]  = sc;  s_red[12 + wid] = scm;
            S[wid] = spe; S[4 + wid] = snp; S[8 + wid] = sco; S[12 + wid] = sgt;
        }
        __syncthreads();
        if (tid == 0) {
            float t0=0,t1=0,t2=0,t3=0,t4=0,t5=0,t6=0,t7=0;
            for (int w = 0; w < 4; w++) {
                t0 += s_red[w]; t1 += s_red[4+w]; t2 += s_red[8+w]; t3 += s_red[12+w];
                t4 += S[w];     t5 += S[4+w];     t6 += S[8+w];     t7 += S[12+w];
            }
            double param_loss  = (double)t0 / 64.0;
            double KLD         = -0.5 * (double)t1 / 64.0 * 10.0;
            double recon_loss  = (double)t2 / 64.0;
            double cmap_loss   = 3000.0 * (double)t3 / (64.0 * (double)t5);
            double consistency = -5.0 * (double)t6 / ((double)t7 + 0.0001);
            double penetr      = 100.0 * (double)t4 / 64.0;
            double loss = (recon_loss + KLD) + 0.1 * param_loss
                        + 1000.0 * cmap_loss + 10.0 * consistency + 10.0 * penetr;
            out[0] = (float)loss;
            g_ticket = 0; g_done = 0; g_mapdone = 0; g_fin = 0;
            __threadfence();
        }
    }
}

extern "C" void kernel_launch(void* const* d_in, const int* in_sizes, int n_in,
                              void* d_out, int out_size) {
    const float* obj   = (const float*)d_in[0];
    const float* recon = (const float*)d_in[1];
    const float* gt    = (const float*)d_in[2];
    const float* mean  = (const float*)d_in[3];
    const float* logv  = (const float*)d_in[4];
    const float* rp    = (const float*)d_in[5];
    const float* xp    = (const float*)d_in[6];
    const int*   faces = (const int*)d_in[7];
    float* out = (float*)d_out;

    k_mega<<<NBLOCKS, TPB>>>(obj, recon, gt, faces, mean, logv, rp, xp, out);
}